// round 4
// baseline (speedup 1.0000x reference)
#include <cuda_runtime.h>
#include <math.h>

#define Bb 2
#define Hh 16
#define Ss 2048
#define Dd 64
#define TQ 16
#define TPB 512
#define KT 128
#define SCP 2049
#define INV_TEMP 0.125f

typedef unsigned long long ull;

// smem layout (float offsets)
#define OFF_Q2 0                         // 1024 floats: q packed as ull[8 pairs][64 d]
#define OFF_SC 1024                      // 16*2049 = 32784 floats
#define OFF_KT (OFF_SC + TQ*SCP)         // 2 tile buffers * 128*64 = 16384 floats (reused for PV partials)
#define OFF_MS (OFF_KT + 2*KT*Dd)        // 64 u32 mask bitmap
#define OFF_BS (OFF_MS + 64)             // 64 u32 prefix bases
#define OFF_NL (OFF_BS + 64)             // 1 int n_live
#define OFF_LJ (OFF_NL + 1)              // 2048 u16 live key indices = 1024 floats
#define SMEM_FLOATS (OFF_LJ + 1024)      // 51345 floats = 205380 B

__device__ __forceinline__ ull pk2(float lo, float hi) {
    ull r; asm("mov.b64 %0,{%1,%2};" : "=l"(r) : "f"(lo), "f"(hi)); return r;
}
__device__ __forceinline__ void upk2(ull v, float& lo, float& hi) {
    asm("mov.b64 {%0,%1},%2;" : "=f"(lo), "=f"(hi) : "l"(v));
}
__device__ __forceinline__ ull fma2(ull a, ull b, ull c) {
    ull d; asm("fma.rn.f32x2 %0,%1,%2,%3;" : "=l"(d) : "l"(a), "l"(b), "l"(c)); return d;
}

__global__ void __launch_bounds__(TPB, 1)
attn_kernel(const float* __restrict__ Q, const float* __restrict__ K,
            const float* __restrict__ V, const float* __restrict__ SENT,
            const int* __restrict__ MASK,
            float* __restrict__ OUT, float* __restrict__ ATTN)
{
    extern __shared__ float smem[];
    ull*            q2    = (ull*)(smem + OFF_Q2);
    float*          sc    = smem + OFF_SC;
    float4*         ktb   = (float4*)(smem + OFF_KT);
    unsigned*       maskw = (unsigned*)(smem + OFF_MS);
    unsigned*       basew = (unsigned*)(smem + OFF_BS);
    int*            nlp   = (int*)(smem + OFF_NL);
    unsigned short* liveJ = (unsigned short*)(smem + OFF_LJ);

    const int tid = threadIdx.x, lane = tid & 31, wid = tid >> 5;
    const int q0 = blockIdx.x * TQ, h = blockIdx.y, b = blockIdx.z;
    const size_t head_off = ((size_t)(b * Hh + h)) * (size_t)Ss;

    // ---- pack q (pre-scaled) into row-pairs: q2[p][d] = {q[2p][d], q[2p+1][d]} ----
    {
        const float* qb = Q + (head_off + (size_t)q0) * Dd;
        for (int i = tid; i < TQ * Dd; i += TPB) {
            int r = i >> 6, d = i & 63;
            ((float*)q2)[((((r >> 1) << 6) + d) << 1) | (r & 1)] = qb[i] * INV_TEMP;
        }
    }
    // ---- mask bitmap ----
    {
        const int* mr = MASK + b * Ss;
        #pragma unroll
        for (int t = 0; t < 4; t++) {
            int j = t * TPB + tid;
            unsigned bl = __ballot_sync(0xFFFFFFFFu, mr[j] != 0);
            if (lane == 0) maskw[t * 16 + wid] = bl;
        }
    }
    __syncthreads();

    // ---- prefix scan + live-key compaction ----
    if (tid == 0) {
        unsigned acc = 0;
        for (int w = 0; w < 64; w++) { basew[w] = acc; acc += __popc(maskw[w]); }
        *nlp = (int)acc;
    }
    __syncthreads();
    const int n_live = *nlp;
    for (int j = tid; j < Ss; j += TPB) {
        unsigned w = maskw[j >> 5];
        if ((w >> (j & 31)) & 1u) {
            int pos = basew[j >> 5] + __popc(w & ((1u << (j & 31)) - 1u));
            liveJ[pos] = (unsigned short)j;
        }
    }
    __syncthreads();

    const int NTL = (n_live + KT - 1) / KT;
    const float4* ksrc = (const float4*)(K + head_off * Dd);
    const float4* vsrc = (const float4*)(V + head_off * Dd);

    float4 pf[4];
    // gather tile t (live keys) into prefetch regs
    auto gather = [&](const float4* src, int t) {
        #pragma unroll
        for (int u = 0; u < 4; u++) {
            int i = u * TPB + tid;
            int s = t * KT + (i >> 4);
            if (s < n_live) pf[u] = src[(size_t)liveJ[s] * 16 + (i & 15)];
            else            pf[u] = make_float4(0.f, 0.f, 0.f, 0.f);
        }
    };
    auto store_tile = [&](int buf) {
        float4* dst = ktb + buf * KT * 16;
        #pragma unroll
        for (int u = 0; u < 4; u++) {
            int i = u * TPB + tid;
            int jj = i >> 4, cc = i & 15;
            dst[jj * 16 + (cc ^ (jj & 7))] = pf[u];
        }
    };

    // ================= Phase 1: scores over live keys =================
    if (NTL > 0) { gather(ksrc, 0); store_tile(0); }
    __syncthreads();
    {
        const int sl = tid >> 2;   // slot within tile
        const int rq = tid & 3;    // row quarter: pairs {2rq, 2rq+1} = rows 4rq..4rq+3
        const ulonglong2* qa  = (const ulonglong2*)(q2 + (2 * rq)     * 64);
        const ulonglong2* qb2 = (const ulonglong2*)(q2 + (2 * rq + 1) * 64);

        for (int t = 0; t < NTL; t++) {
            if (t + 1 < NTL) gather(ksrc, t + 1);
            const int s = t * KT + sl;
            const float4* kb = ktb + (t & 1) * KT * 16;
            if (s < n_live) {
                const int j = liveJ[s];
                ull a0 = 0ull, a1 = 0ull;
                const int sw = sl & 7;
                #pragma unroll
                for (int c = 0; c < 16; c++) {
                    float4 kv = kb[sl * 16 + (c ^ sw)];
                    ull s0 = pk2(kv.x, kv.x), s1 = pk2(kv.y, kv.y);
                    ull s2 = pk2(kv.z, kv.z), s3 = pk2(kv.w, kv.w);
                    ulonglong2 qa0 = qa[2 * c],  qa1 = qa[2 * c + 1];
                    ulonglong2 qb0 = qb2[2 * c], qb1 = qb2[2 * c + 1];
                    a0 = fma2(qa0.x, s0, a0); a0 = fma2(qa0.y, s1, a0);
                    a0 = fma2(qa1.x, s2, a0); a0 = fma2(qa1.y, s3, a0);
                    a1 = fma2(qb0.x, s0, a1); a1 = fma2(qb0.y, s1, a1);
                    a1 = fma2(qb1.x, s2, a1); a1 = fma2(qb1.y, s3, a1);
                }
                float x, y;
                upk2(a0, x, y);
                sc[(4 * rq + 0) * SCP + j] = x; sc[(4 * rq + 1) * SCP + j] = y;
                upk2(a1, x, y);
                sc[(4 * rq + 2) * SCP + j] = x; sc[(4 * rq + 3) * SCP + j] = y;
            }
            if (t + 1 < NTL) store_tile((t + 1) & 1);
            __syncthreads();
        }
    }

    // ===== Phase 2: p = exp(s-m)*sent / sum over live; masked = 0; write ATTN =====
    {
        const int r = wid;            // 16 warps = 16 rows
        float* row = sc + r * SCP;
        float m = -INFINITY;
        for (int jj = lane; jj < Ss; jj += 32)
            if ((maskw[jj >> 5] >> (jj & 31)) & 1u) m = fmaxf(m, row[jj]);
        #pragma unroll
        for (int o = 16; o; o >>= 1) m = fmaxf(m, __shfl_xor_sync(0xFFFFFFFFu, m, o));

        const float* srow = SENT + b * Ss;
        float sum = 0.f;
        for (int jj = lane; jj < Ss; jj += 32) {
            float p = 0.f;
            if ((maskw[jj >> 5] >> (jj & 31)) & 1u) p = __expf(row[jj] - m) * srow[jj];
            row[jj] = p;
            sum += p;
        }
        #pragma unroll
        for (int o = 16; o; o >>= 1) sum += __shfl_xor_sync(0xFFFFFFFFu, sum, o);
        const float inv = 1.0f / sum;

        float* arow = ATTN + (head_off + (size_t)(q0 + r)) * (size_t)Ss;
        for (int jj = lane; jj < Ss; jj += 32) {
            float a = row[jj] * inv;
            row[jj] = a;
            arow[jj] = a;
        }
    }
    __syncthreads();

    // ================= Phase 3: out = probs @ V over live keys =================
    {
        const int r = lane & 15, dh = lane >> 4;  // warp covers 16 rows x 2 d-halves
        ull acc[16];
        #pragma unroll
        for (int i = 0; i < 16; i++) acc[i] = 0ull;

        if (NTL > 0) { gather(vsrc, 0); store_tile(0); }
        __syncthreads();

        for (int t = 0; t < NTL; t++) {
            if (t + 1 < NTL) gather(vsrc, t + 1);
            const ulonglong2* vb = (const ulonglong2*)(ktb + (t & 1) * KT * 16);
            #pragma unroll 2
            for (int i = 0; i < 8; i++) {
                const int s = t * KT + wid * 8 + i;   // warp-uniform slot
                if (s < n_live) {
                    const int jl = wid * 8 + i;
                    const int j  = liveJ[s];
                    float p = sc[r * SCP + j];
                    ull pp = pk2(p, p);
                    const int sw = jl & 7;
                    #pragma unroll
                    for (int c = 0; c < 8; c++) {
                        ulonglong2 vv = vb[jl * 16 + ((dh * 8 + c) ^ sw)];
                        acc[2 * c]     = fma2(pp, vv.x, acc[2 * c]);
                        acc[2 * c + 1] = fma2(pp, vv.y, acc[2 * c + 1]);
                    }
                }
            }
            if (t + 1 < NTL) store_tile((t + 1) & 1);
            __syncthreads();
        }

        // per-warp partials -> smem (swizzled) -> reduce over 16 warps
        ulonglong2* part2 = (ulonglong2*)(smem + OFF_KT);
        const int b2 = (wid * 32 + lane) * 8;
        #pragma unroll
        for (int ip = 0; ip < 8; ip++) {
            ulonglong2 v; v.x = acc[2 * ip]; v.y = acc[2 * ip + 1];
            part2[b2 + (ip ^ (lane & 7))] = v;
        }
        __syncthreads();

        if (tid < 256) {
            const int rr = tid >> 4, cq = tid & 15;
            const int dh2 = cq >> 3, ip = cq & 7;
            const int ln = rr + 16 * dh2;
            float4 s = make_float4(0.f, 0.f, 0.f, 0.f);
            #pragma unroll
            for (int g = 0; g < 16; g++) {
                float4 p = *(const float4*)&part2[(g * 32 + ln) * 8 + (ip ^ (ln & 7))];
                s.x += p.x; s.y += p.y; s.z += p.z; s.w += p.w;
            }
            ((float4*)(OUT + (head_off + (size_t)(q0 + rr)) * Dd))[cq] = s;
        }
    }
}

extern "C" void kernel_launch(void* const* d_in, const int* in_sizes, int n_in,
                              void* d_out, int out_size)
{
    const float* q    = (const float*)d_in[0];
    const float* k    = (const float*)d_in[1];
    const float* v    = (const float*)d_in[2];
    const float* sent = (const float*)d_in[3];
    const int*   mask = (const int*)d_in[4];

    float* out  = (float*)d_out;                    // [B,H,S,D]
    float* attn = out + (size_t)Bb * Hh * Ss * Dd;  // [B,H,S,S]

    size_t smem_bytes = (size_t)SMEM_FLOATS * sizeof(float); // 205380 B
    cudaFuncSetAttribute(attn_kernel,
                         cudaFuncAttributeMaxDynamicSharedMemorySize,
                         (int)smem_bytes);

    dim3 grid(Ss / TQ, Hh, Bb);
    attn_kernel<<<grid, TPB, smem_bytes>>>(q, k, v, sent, mask, out, attn);
}

// round 6
// speedup vs baseline: 4.0128x; 4.0128x over previous
#include <cuda_runtime.h>
#include <cuda_bf16.h>
#include <cstdint>
#include <math.h>

#define Bb 2
#define Hh 16
#define Ss 2048
#define Dd 64
#define MT 128
#define KN 128
#define NTL (Ss/KN)
#define TPB 256
#define INV_TEMP 0.125f

// SMEM byte offsets
#define SM_QH 0
#define SM_QL 16384
#define SM_KH 32768
#define SM_KL 49152
#define SM_VH 65536
#define SM_VL 81920
#define SM_RAWK 98304
#define SM_RAWV 131072
#define SM_SENT 163840
#define SM_RINV 164352
#define SMEM_BYTES 164864

__device__ __forceinline__ uint32_t smem_u32(const void* p) {
    uint32_t a; asm("{ .reg .u64 t; cvta.to.shared.u64 t, %1; cvt.u32.u64 %0, t; }" : "=r"(a) : "l"(p));
    return a;
}
__device__ __forceinline__ uint32_t sw128(uint32_t off) { return off ^ ((off >> 3) & 0x70); }

__device__ __forceinline__ void split2(float x0, float x1, uint32_t& hi, uint32_t& lo) {
    __nv_bfloat16 h0 = __float2bfloat16(x0), h1 = __float2bfloat16(x1);
    float r0 = x0 - __bfloat162float(h0), r1 = x1 - __bfloat162float(h1);
    __nv_bfloat162 H; H.x = h0; H.y = h1;
    __nv_bfloat162 L; L.x = __float2bfloat16(r0); L.y = __float2bfloat16(r1);
    hi = *(uint32_t*)&H; lo = *(uint32_t*)&L;
}

__device__ __forceinline__ void ldsm4(uint32_t* r, uint32_t addr) {
    asm volatile("ldmatrix.sync.aligned.m8n8.x4.shared.b16 {%0,%1,%2,%3}, [%4];"
        : "=r"(r[0]), "=r"(r[1]), "=r"(r[2]), "=r"(r[3]) : "r"(addr));
}
__device__ __forceinline__ void ldsm4t(uint32_t* r, uint32_t addr) {
    asm volatile("ldmatrix.sync.aligned.m8n8.x4.trans.shared.b16 {%0,%1,%2,%3}, [%4];"
        : "=r"(r[0]), "=r"(r[1]), "=r"(r[2]), "=r"(r[3]) : "r"(addr));
}
__device__ __forceinline__ void mma16816(float* c, const uint32_t* a, uint32_t b0, uint32_t b1) {
    asm volatile("mma.sync.aligned.m16n8k16.row.col.f32.bf16.bf16.f32 "
        "{%0,%1,%2,%3}, {%4,%5,%6,%7}, {%8,%9}, {%0,%1,%2,%3};"
        : "+f"(c[0]), "+f"(c[1]), "+f"(c[2]), "+f"(c[3])
        : "r"(a[0]), "r"(a[1]), "r"(a[2]), "r"(a[3]), "r"(b0), "r"(b1));
}
__device__ __forceinline__ void cp16(uint32_t saddr, const void* g) {
    asm volatile("cp.async.ca.shared.global [%0], [%1], 16;" :: "r"(saddr), "l"(g));
}
#define CP_COMMIT() asm volatile("cp.async.commit_group;" ::: "memory")
#define CP_WAIT0()  asm volatile("cp.async.wait_group 0;" ::: "memory")

__global__ void __launch_bounds__(TPB, 1)
attn_kernel(const float* __restrict__ Q, const float* __restrict__ K,
            const float* __restrict__ V, const float* __restrict__ SENT,
            const int* __restrict__ MASK,
            float* __restrict__ OUT, float* __restrict__ ATTN)
{
    extern __shared__ char sm[];
    const uint32_t sb = smem_u32(sm);
    const int tid = threadIdx.x, lane = tid & 31, wid = tid >> 5;
    const int q0 = blockIdx.x * MT;
    const int head = blockIdx.y;
    const int b = head >> 4;
    const size_t head_off = (size_t)head * Ss;

    float* sentm = (float*)(sm + SM_SENT);
    float* rinv  = (float*)(sm + SM_RINV);

    // ---- stage Q -> bf16 hi/lo, swizzled (pre-scaled by 1/T) ----
    {
        const float4* qg = (const float4*)(Q + (head_off + q0) * Dd);
        #pragma unroll
        for (int u = 0; u < 4; u++) {
            int idx = u * TPB + tid;
            int r = idx >> 3, c = idx & 7;
            float4 a = qg[r * 16 + c * 2], bq = qg[r * 16 + c * 2 + 1];
            uint4 H, L;
            split2(a.x * INV_TEMP, a.y * INV_TEMP, H.x, L.x);
            split2(a.z * INV_TEMP, a.w * INV_TEMP, H.y, L.y);
            split2(bq.x * INV_TEMP, bq.y * INV_TEMP, H.z, L.z);
            split2(bq.z * INV_TEMP, bq.w * INV_TEMP, H.w, L.w);
            uint32_t off = sw128((uint32_t)(r * 128 + c * 16));
            *(uint4*)(sm + SM_QH + off) = H;
            *(uint4*)(sm + SM_QL + off) = L;
        }
    }
    // prefetch raw K/V tile 0
    {
        const char* kg = (const char*)(K + head_off * Dd);
        const char* vg = (const char*)(V + head_off * Dd);
        #pragma unroll
        for (int u = 0; u < 8; u++) {
            int i = u * TPB + tid;
            cp16(sb + SM_RAWK + i * 16, kg + i * 16);
            cp16(sb + SM_RAWV + i * 16, vg + i * 16);
        }
        CP_COMMIT();
    }
    __syncthreads();

    // ---- load Q fragments (held all kernel) ----
    uint32_t qh[4][4], ql[4][4];
    {
        uint32_t rowq = (uint32_t)(wid * 16 + (lane & 15));
        #pragma unroll
        for (int kb = 0; kb < 4; kb++) {
            uint32_t off = sw128(rowq * 128 + ((uint32_t)(lane >> 4) + 2 * kb) * 16);
            ldsm4(qh[kb], sb + SM_QH + off);
            ldsm4(ql[kb], sb + SM_QL + off);
        }
    }
    CP_WAIT0();
    __syncthreads();

    float oacc[8][4];
    #pragma unroll
    for (int nb = 0; nb < 8; nb++)
        #pragma unroll
        for (int i = 0; i < 4; i++) oacc[nb][i] = 0.f;
    float rsum0 = 0.f, rsum1 = 0.f;

    const int row0 = wid * 16 + (lane >> 2);
    const int cb = 2 * (lane & 3);
    float* arow0 = ATTN + (head_off + q0 + row0) * (size_t)Ss;
    float* arow1 = arow0 + 8 * (size_t)Ss;

    for (int t = 0; t < NTL; t++) {
        const int j0 = t * KN;
        // ---- convert raw -> bf16 hi/lo ----
        {
            const float4* rk = (const float4*)(sm + SM_RAWK);
            const float4* rv = (const float4*)(sm + SM_RAWV);
            #pragma unroll
            for (int u = 0; u < 4; u++) {
                int idx = u * TPB + tid;
                int r = idx >> 3, c = idx & 7;
                uint32_t off = sw128((uint32_t)(r * 128 + c * 16));
                float4 a = rk[r * 16 + c * 2], bq = rk[r * 16 + c * 2 + 1];
                uint4 H, L;
                split2(a.x, a.y, H.x, L.x);  split2(a.z, a.w, H.y, L.y);
                split2(bq.x, bq.y, H.z, L.z); split2(bq.z, bq.w, H.w, L.w);
                *(uint4*)(sm + SM_KH + off) = H;
                *(uint4*)(sm + SM_KL + off) = L;
                a = rv[r * 16 + c * 2]; bq = rv[r * 16 + c * 2 + 1];
                split2(a.x, a.y, H.x, L.x);  split2(a.z, a.w, H.y, L.y);
                split2(bq.x, bq.y, H.z, L.z); split2(bq.z, bq.w, H.w, L.w);
                *(uint4*)(sm + SM_VH + off) = H;
                *(uint4*)(sm + SM_VL + off) = L;
            }
            if (tid < KN)
                sentm[tid] = MASK[b * Ss + j0 + tid] ? SENT[b * Ss + j0 + tid] : 0.0f;
        }
        __syncthreads();

        // prefetch next raw tile
        if (t + 1 < NTL) {
            const char* kg = (const char*)(K + (head_off + j0 + KN) * Dd);
            const char* vg = (const char*)(V + (head_off + j0 + KN) * Dd);
            #pragma unroll
            for (int u = 0; u < 8; u++) {
                int i = u * TPB + tid;
                cp16(sb + SM_RAWK + i * 16, kg + i * 16);
                cp16(sb + SM_RAWV + i * 16, vg + i * 16);
            }
            CP_COMMIT();
        }

        // ---- QK + epilogue per 8-key block ----
        uint32_t pah[8][4], pal[8][4];
        #pragma unroll
        for (int nb = 0; nb < 16; nb++) {
            float sacc[4] = {0.f, 0.f, 0.f, 0.f};
            uint32_t bh[8], bl[8];
            uint32_t rB = (uint32_t)(nb * 8 + (lane & 7)) * 128;
            uint32_t ch = (uint32_t)(lane >> 3) * 16;
            ldsm4(bh,     sb + SM_KH + sw128(rB + ch));
            ldsm4(bh + 4, sb + SM_KH + sw128(rB + ch + 64));
            ldsm4(bl,     sb + SM_KL + sw128(rB + ch));
            ldsm4(bl + 4, sb + SM_KL + sw128(rB + ch + 64));
            #pragma unroll
            for (int kb = 0; kb < 4; kb++) {
                mma16816(sacc, qh[kb], bh[2 * kb], bh[2 * kb + 1]);
                mma16816(sacc, qh[kb], bl[2 * kb], bl[2 * kb + 1]);
                mma16816(sacc, ql[kb], bh[2 * kb], bh[2 * kb + 1]);
            }
            // epilogue: p = exp(s) * sent*mask
            float2 s2 = *(float2*)&sentm[nb * 8 + cb];
            float p0 = __expf(sacc[0]) * s2.x;
            float p1 = __expf(sacc[1]) * s2.y;
            float p2 = __expf(sacc[2]) * s2.x;
            float p3 = __expf(sacc[3]) * s2.y;
            rsum0 += p0 + p1; rsum1 += p2 + p3;
            *(float2*)(arow0 + j0 + nb * 8 + cb) = make_float2(p0, p1);
            *(float2*)(arow1 + j0 + nb * 8 + cb) = make_float2(p2, p3);
            const int kb = nb >> 1, hf = (nb & 1) * 2;
            split2(p0, p1, pah[kb][hf],     pal[kb][hf]);
            split2(p2, p3, pah[kb][hf + 1], pal[kb][hf + 1]);
        }

        // ---- PV ----
        #pragma unroll
        for (int kb = 0; kb < 8; kb++) {
            uint32_t vh[16], vl[16];
            uint32_t rV = (uint32_t)(kb * 16 + (lane & 15)) * 128;
            uint32_t chv = (uint32_t)(lane >> 4) * 16;
            #pragma unroll
            for (int qd = 0; qd < 4; qd++) {
                ldsm4t(vh + 4 * qd, sb + SM_VH + sw128(rV + chv + qd * 32));
                ldsm4t(vl + 4 * qd, sb + SM_VL + sw128(rV + chv + qd * 32));
            }
            #pragma unroll
            for (int nb = 0; nb < 8; nb++) {
                mma16816(oacc[nb], pah[kb], vh[2 * nb], vh[2 * nb + 1]);
                mma16816(oacc[nb], pal[kb], vh[2 * nb], vh[2 * nb + 1]);
                mma16816(oacc[nb], pah[kb], vl[2 * nb], vl[2 * nb + 1]);
            }
        }

        if (t + 1 < NTL) CP_WAIT0();
        __syncthreads();
    }

    // ---- finalize rowsums ----
    rsum0 += __shfl_xor_sync(0xFFFFFFFFu, rsum0, 1);
    rsum0 += __shfl_xor_sync(0xFFFFFFFFu, rsum0, 2);
    rsum1 += __shfl_xor_sync(0xFFFFFFFFu, rsum1, 1);
    rsum1 += __shfl_xor_sync(0xFFFFFFFFu, rsum1, 2);
    const float inv0 = 1.0f / rsum0, inv1 = 1.0f / rsum1;
    if ((lane & 3) == 0) {
        rinv[row0] = inv0;
        rinv[row0 + 8] = inv1;
    }

    // ---- write out = acc / rowsum ----
    {
        float2* o0 = (float2*)(OUT + (head_off + q0 + row0) * (size_t)Dd);
        float2* o1 = (float2*)(OUT + (head_off + q0 + row0 + 8) * (size_t)Dd);
        #pragma unroll
        for (int nb = 0; nb < 8; nb++) {
            o0[nb * 4 + (lane & 3)] = make_float2(oacc[nb][0] * inv0, oacc[nb][1] * inv0);
            o1[nb * 4 + (lane & 3)] = make_float2(oacc[nb][2] * inv1, oacc[nb][3] * inv1);
        }
    }
    __syncthreads();

    // ---- rescale attn strip ----
    {
        float4* a4 = (float4*)(ATTN + (head_off + q0) * (size_t)Ss);
        #pragma unroll 4
        for (int idx = tid; idx < MT * (Ss / 4); idx += TPB) {
            float s = rinv[idx >> 9];
            float4 v = a4[idx];
            v.x *= s; v.y *= s; v.z *= s; v.w *= s;
            a4[idx] = v;
        }
    }
}

extern "C" void kernel_launch(void* const* d_in, const int* in_sizes, int n_in,
                              void* d_out, int out_size)
{
    const float* q    = (const float*)d_in[0];
    const float* k    = (const float*)d_in[1];
    const float* v    = (const float*)d_in[2];
    const float* sent = (const float*)d_in[3];
    const int*   mask = (const int*)d_in[4];

    float* out  = (float*)d_out;                    // [B,H,S,D]
    float* attn = out + (size_t)Bb * Hh * Ss * Dd;  // [B,H,S,S]

    cudaFuncSetAttribute(attn_kernel, cudaFuncAttributeMaxDynamicSharedMemorySize, SMEM_BYTES);

    dim3 grid(Ss / MT, Bb * Hh);
    attn_kernel<<<grid, TPB, SMEM_BYTES>>>(q, k, v, sent, mask, out, attn);
}